// round 10
// baseline (speedup 1.0000x reference)
#include <cuda_runtime.h>
#include <cuda_fp16.h>
#include <stdint.h>

#define BATCH 16
#define CIN   256
#define COUT  256
#define HW    1024
#define NE    8
#define NCHUNK 36             /* 9 taps * 4 ci-quarters of 64 */
#define STAGE  32768          /* A 16KB + B 16KB */
#define NSTAGE 4
#define SMEM_TOTAL (NSTAGE * STAGE + 1024)

// ---------------- helpers ----------------
__device__ __forceinline__ uint32_t smem_u32(const void* p) {
    uint32_t a;
    asm("{ .reg .u64 t; cvta.to.shared.u64 t, %1; cvt.u32.u64 %0, t; }" : "=r"(a) : "l"(p));
    return a;
}
#define SWZ(off) ((off) ^ (((off) >> 3) & 0x70))

#define CP_ASYNC16(dst, src) \
    asm volatile("cp.async.cg.shared.global [%0], [%1], 16;" :: "r"(dst), "l"(src) : "memory")
#define CP_COMMIT() asm volatile("cp.async.commit_group;" ::: "memory")
#define CP_WAIT2()  asm volatile("cp.async.wait_group 2;" ::: "memory")

#define LDSM_X4(r, addr) \
    asm volatile("ldmatrix.sync.aligned.m8n8.x4.shared.b16 {%0,%1,%2,%3}, [%4];" \
        : "=r"((r)[0]), "=r"((r)[1]), "=r"((r)[2]), "=r"((r)[3]) : "r"(addr))

#define MMA16816(d, a, b0, b1) \
    asm volatile("mma.sync.aligned.m16n8k16.row.col.f32.f16.f16.f32 " \
        "{%0,%1,%2,%3}, {%4,%5,%6,%7}, {%8,%9}, {%0,%1,%2,%3};" \
        : "+f"((d)[0]), "+f"((d)[1]), "+f"((d)[2]), "+f"((d)[3]) \
        : "r"((a)[0]), "r"((a)[1]), "r"((a)[2]), "r"((a)[3]), "r"(b0), "r"(b1))

// ---------------- device scratch ----------------
__device__ int g_decisions[BATCH];
__device__ float g_pooled[BATCH * CIN];
// weights, tap-major fp16 pairs: [e][t][co][ci/2] u32
__device__ __align__(256) uint32_t g_wh[(size_t)NE * 9 * COUT * 128];            // 9.4 MB
// padded+shifted X, pixel-major fp16 pairs: [i][dx 3][34 y][32 px][128 ci-pairs]
__device__ __align__(256) uint32_t g_xq[(size_t)BATCH * 3 * 34 * 32 * 128];      // 26.7 MB

__device__ __forceinline__ uint32_t pack2(float v0, float v1) {
    __half h0 = __float2half_rn(v0), h1 = __float2half_rn(v1);
    return ((uint32_t)__half_as_ushort(h1) << 16) | __half_as_ushort(h0);
}

// ---------------- kernel 1: fused prep ----------------
// blocks [0,544): (i = b/34, y = b%34) -> g_xq rows + pooling partial
// blocks [544, 544+2048): weight row (e*256+co) -> [e][t][co][ci]
__global__ void prep_kernel(const float* __restrict__ x, const float* __restrict__ we) {
    __shared__ float sX[32 * 257];               // [px][ci] padded, 32.9 KB
    const int b = blockIdx.x, tid = threadIdx.x;
    if (b < 544) {
        const int i = b / 34, y = b % 34;        // g_xq row y holds x image row y-1
        const bool valid = (y >= 1 && y <= 32);
        if (valid) {
            const float* src = x + (size_t)i * CIN * HW + (size_t)(y - 1) * 32;
            for (int idx = tid; idx < 8192; idx += 256) {
                int ci = idx >> 5, px = idx & 31;
                sX[px * 257 + ci] = src[(size_t)ci * HW + px];
            }
        }
        __syncthreads();

        if (valid) {   // pooled partial: thread ci sums one row of 32 px
            float s = 0.f;
            #pragma unroll 8
            for (int px = 0; px < 32; px++) s += sX[px * 257 + tid];
            atomicAdd(&g_pooled[i * CIN + tid], s * (1.0f / HW));
        }

        // write 3 dx shifts: [dx][px][128 ci-pairs]
        uint32_t* dst = g_xq + (((size_t)i * 3) * 34 + y) * 32 * 128;
        for (int idx = tid; idx < 3 * 32 * 128; idx += 256) {
            int cp = idx & 127;
            int px = (idx >> 7) & 31;
            int dx = idx >> 12;
            float v0 = 0.f, v1 = 0.f;
            int sxp = px + dx - 1;
            if (valid && (unsigned)sxp < 32u) {
                v0 = sX[sxp * 257 + 2 * cp];
                v1 = sX[sxp * 257 + 2 * cp + 1];
            }
            dst[((size_t)dx * 34 * 32 + px) * 128 + cp] = pack2(v0, v1);
        }
    } else {
        __shared__ float sW[2304];
        const int row = b - 544;                  // e*256+co
        const int e = row >> 8, co = row & 255;
        const float* src = we + (size_t)row * 2304;
        for (int k = tid; k < 2304; k += 256) sW[k] = src[k];
        __syncthreads();
        for (int idx = tid; idx < 9 * 128; idx += 256) {
            int t = idx >> 7, cip = idx & 127;
            int ci0 = cip * 2;
            g_wh[((size_t)(e * 9 + t) * COUT + co) * 128 + cip] =
                pack2(sW[ci0 * 9 + t], sW[(ci0 + 1) * 9 + t]);
        }
    }
}

// ---------------- kernel 2: router finish ----------------
__global__ void router_finish_kernel(const float* __restrict__ wc,
                                     const float* __restrict__ bc) {
    __shared__ float sLog[BATCH][NE];
    const int tid = threadIdx.x;
    const int b = tid >> 3, e = tid & 7;
    const float* p = g_pooled + b * CIN;
    const float* w = wc + e * CIN;
    float sum = 0.f;
    #pragma unroll 8
    for (int k = 0; k < CIN; k++) sum += p[k] * w[k];
    sLog[b][e] = sum + bc[e];
    __syncthreads();
    if (tid < BATCH) {
        float best = sLog[tid][0]; int bi = 0;
        #pragma unroll
        for (int ee = 1; ee < NE; ee++)
            if (sLog[tid][ee] > best) { best = sLog[tid][ee]; bi = ee; }
        g_decisions[tid] = bi;
    }
}

// ---------------- kernel 3: HMMA implicit GEMM, all non-trans ldsm ----------
// CTA tile 128co x 128px; 8 warps (2co x 4px) of 64x32. 4-stage cp.async.
// B smem: [128 px][64 ci = 128B row] SW128 -> non-trans ldsm gives col-B frags.
// grid (8 px-tiles of 128, 2 co-tiles of 128, 128 pairs), 256 threads.
__global__ void __launch_bounds__(256, 1)
gemm_kernel(const float* __restrict__ be, float* __restrict__ out) {
    extern __shared__ __align__(16) char dynraw[];
    char* dyn = (char*)(((uintptr_t)dynraw + 1023) & ~(uintptr_t)1023);
    const uint32_t dynu = smem_u32(dyn);

    __shared__ int sDec[BATCH];
    const int tid = threadIdx.x;
    const int ntile = blockIdx.x, mtile = blockIdx.y, pair = blockIdx.z;
    const int i = pair & 15, e = pair >> 4;

    if (tid < BATCH) sDec[tid] = g_decisions[tid];
    __syncthreads();
    bool need = false;
    #pragma unroll
    for (int j = 0; j < BATCH; j++) need |= (sDec[j] == e);
    if (!need) return;

    const int lane = tid & 31, wid = tid >> 5;
    const int wm = wid & 1, wn = wid >> 1;     // 2x4 warps, 64co x 32px each
    const int y0 = ntile << 2;                 // first image row of 128-px tile

    float acc[4][4][4];
    #pragma unroll
    for (int ma = 0; ma < 4; ma++)
        #pragma unroll
        for (int na = 0; na < 4; na++)
            #pragma unroll
            for (int c = 0; c < 4; c++) acc[ma][na][c] = 0.f;

    // A fragment base: rows=co 128B SW128 (lane 0-15 rows, lane>>4 k-half)
    const uint32_t aFragBase = (uint32_t)((wm * 64 + (lane & 15)) * 128 + ((lane >> 4) << 4));
    // B fragment base (non-trans): rows = px, cols = k-halves
    // lane l -> px row = wn*32 + pb*16 + ((l>>4)<<3) + (l&7), col16 = (l>>3)&1
    uint32_t bFragBase[2];
    #pragma unroll
    for (int pb = 0; pb < 2; pb++) {
        int pxr = wn * 32 + pb * 16 + ((lane >> 4) << 3) + (lane & 7);
        bFragBase[pb] = (uint32_t)(pxr * 128 + (((lane >> 3) & 1) << 4));
    }

    // gmem->smem maps (256 threads, 4 x 16B each per operand)
    const int ldcA = tid & 7;                   // A: 8 x 16B per 128B row
    const int coL0 = tid >> 3;                  // rows 0..31, +32 per round
    const int bRow = tid >> 1;                  // B: rows 0..127 (2 thr/row)
    const int bCol0 = (tid & 1) * 4;            // 4 of 8 16B-chunks

    auto load_stage = [&](int buf, int it) {
        const int t = it >> 2, qc = it & 3;
        const int ty = t / 3, tx = t % 3;
        const uint32_t st = dynu + buf * STAGE;
        // A: [128 co][64 ci = 128B]
        const uint32_t* wrow = g_wh + ((size_t)(e * 9 + t) * COUT + (mtile << 7) + coL0) * 128
                               + (qc << 5) + ldcA * 4;
        #pragma unroll
        for (int r = 0; r < 4; r++)
            CP_ASYNC16(st + SWZ((coL0 + r * 32) * 128 + ldcA * 16),
                       (const char*)(wrow + (size_t)r * 32 * 128));
        // B: [128 px][64 ci = 128B]; px rows contiguous (512B stride) in g_xq
        const char* xbase = (const char*)g_xq
            + ((((size_t)(i * 3 + tx) * 34 + y0 + ty) * 32) << 9)   // *512B
            + (qc << 7) + (size_t)bRow * 512;
        #pragma unroll
        for (int c = 0; c < 4; c++)
            CP_ASYNC16(st + 16384 + SWZ(bRow * 128 + (bCol0 + c) * 16),
                       xbase + (bCol0 + c) * 16);
    };

    load_stage(0, 0); CP_COMMIT();
    load_stage(1, 1); CP_COMMIT();
    load_stage(2, 2); CP_COMMIT();

    uint32_t af[2][4][4], bf[2][2][4];
    #pragma unroll 1
    for (int it = 0; it < NCHUNK; ++it) {
        CP_WAIT2();
        __syncthreads();
        if (it + 3 < NCHUNK) load_stage((it + 3) & 3, it + 3);
        CP_COMMIT();

        const uint32_t bA = dynu + (it & 3) * STAGE;
        const uint32_t bB = bA + 16384;

        // prime s=0 fragments
        #pragma unroll
        for (int ma = 0; ma < 4; ma++)
            LDSM_X4(af[0][ma], bA + SWZ(aFragBase + ma * 2048));
        #pragma unroll
        for (int pb = 0; pb < 2; pb++)
            LDSM_X4(bf[0][pb], bB + SWZ(bFragBase[pb]));

        #pragma unroll
        for (int s = 0; s < 4; s++) {
            const int cur = s & 1, nxt = cur ^ 1;
            if (s < 3) {
                #pragma unroll
                for (int ma = 0; ma < 4; ma++)
                    LDSM_X4(af[nxt][ma], bA + SWZ(aFragBase + ma * 2048 + (s + 1) * 32));
                #pragma unroll
                for (int pb = 0; pb < 2; pb++)
                    LDSM_X4(bf[nxt][pb], bB + SWZ(bFragBase[pb] + (s + 1) * 32));
            }
            #pragma unroll
            for (int ma = 0; ma < 4; ma++)
                #pragma unroll
                for (int pb = 0; pb < 2; pb++) {
                    MMA16816(acc[ma][pb * 2],     af[cur][ma], bf[cur][pb][0], bf[cur][pb][1]);
                    MMA16816(acc[ma][pb * 2 + 1], af[cur][ma], bf[cur][pb][2], bf[cur][pb][3]);
                }
        }
    }

    // ---------------- epilogue ----------------
    const int coBase = (mtile << 7) + wm * 64 + (lane >> 2);
    const int pixBase = (ntile << 7) + wn * 32 + 2 * (lane & 3);
    float bias0[4], bias1[4];
    #pragma unroll
    for (int ma = 0; ma < 4; ma++) {
        bias0[ma] = be[(e << 8) + coBase + ma * 16];
        bias1[ma] = be[(e << 8) + coBase + ma * 16 + 8];
    }
    #pragma unroll 1
    for (int j = 0; j < BATCH; j++) {
        if (sDec[j] != e) continue;
        float* ob = out + ((size_t)(j * BATCH + i) << 18);
        #pragma unroll
        for (int ma = 0; ma < 4; ma++) {
            const int co = coBase + ma * 16;
            #pragma unroll
            for (int na = 0; na < 4; na++) {
                const int pix = pixBase + na * 8;
                float2 v0, v1;
                v0.x = fmaxf(acc[ma][na][0] + bias0[ma], 0.f);
                v0.y = fmaxf(acc[ma][na][1] + bias0[ma], 0.f);
                v1.x = fmaxf(acc[ma][na][2] + bias1[ma], 0.f);
                v1.y = fmaxf(acc[ma][na][3] + bias1[ma], 0.f);
                *(float2*)(ob + (size_t)co * HW + pix)       = v0;
                *(float2*)(ob + (size_t)(co + 8) * HW + pix) = v1;
            }
        }
    }
}

// ---------------------------------------------------------------------------
extern "C" void kernel_launch(void* const* d_in, const int* in_sizes, int n_in,
                              void* d_out, int out_size) {
    const float* x  = (const float*)d_in[0];
    const float* wc = (const float*)d_in[1];
    const float* bc = (const float*)d_in[2];
    const float* we = (const float*)d_in[3];
    const float* be = (const float*)d_in[4];
    float* out = (float*)d_out;

    static int smemSet = 0;
    if (!smemSet) {
        cudaFuncSetAttribute(gemm_kernel, cudaFuncAttributeMaxDynamicSharedMemorySize,
                             SMEM_TOTAL);
        smemSet = 1;
    }

    void* pooledPtr = nullptr;
    cudaGetSymbolAddress(&pooledPtr, g_pooled);
    cudaMemsetAsync(pooledPtr, 0, BATCH * CIN * sizeof(float));

    prep_kernel<<<544 + NE * COUT, 256>>>(x, we);
    router_finish_kernel<<<1, 128>>>(wc, bc);
    gemm_kernel<<<dim3(8, 2, BATCH * NE), 256, SMEM_TOTAL>>>(be, out);
}

// round 13
// speedup vs baseline: 1.1316x; 1.1316x over previous
#include <cuda_runtime.h>
#include <cuda_fp16.h>
#include <stdint.h>

#define BATCH 16
#define CIN   256
#define COUT  256
#define HW    1024
#define NE    8
#define NCHUNK 32
#define STAGE  32768
#define NSTAGE 4
#define SMEM_TOTAL (NSTAGE * STAGE + 1024)

__device__ __forceinline__ uint32_t smem_u32(const void* p) {
    uint32_t a;
    asm("{ .reg .u64 t; cvta.to.shared.u64 t, %1; cvt.u32.u64 %0, t; }" : "=r"(a) : "l"(p));
    return a;
}
#define SWZ(off) ((off) ^ (((off) >> 3) & 0x70))

#define CP_ASYNC16(dst, src) \
    asm volatile("cp.async.cg.shared.global [%0], [%1], 16;" :: "r"(dst), "l"(src) : "memory")
#define CP_COMMIT() asm volatile("cp.async.commit_group;" ::: "memory")
#define CP_WAIT2()  asm volatile("cp.async.wait_group 2;" ::: "memory")

#define LDSM_X4(r, addr) \
    asm volatile("ldmatrix.sync.aligned.m8n8.x4.shared.b16 {%0,%1,%2,%3}, [%4];" \
        : "=r"((r)[0]), "=r"((r)[1]), "=r"((r)[2]), "=r"((r)[3]) : "r"(addr))

#define MMA16816(d, a, b0, b1) \
    asm volatile("mma.sync.aligned.m16n8k16.row.col.f32.f16.f16.f32 " \
        "{%0,%1,%2,%3}, {%4,%5,%6,%7}, {%8,%9}, {%0,%1,%2,%3};" \
        : "+f"((d)[0]), "+f"((d)[1]), "+f"((d)[2]), "+f"((d)[3]) \
        : "r"((a)[0]), "r"((a)[1]), "r"((a)[2]), "r"((a)[3]), "r"(b0), "r"(b1))

__device__ int g_decisions[BATCH];
__device__ float g_pooled[BATCH * CIN];
__device__ __align__(256) __half g_U[(size_t)NE * 16 * COUT * CIN];     // U[e][k][co][ci]
__device__ __align__(256) __half g_V[(size_t)BATCH * 16 * 256 * CIN];   // V[i][k][tile][ci]

__device__ __forceinline__ uint32_t pack2(float v0, float v1) {
    __half h0 = __float2half_rn(v0), h1 = __float2half_rn(v1);
    return ((uint32_t)__half_as_ushort(h1) << 16) | __half_as_ushort(h0);
}

// ---------------- kernel 1: prep (V transform + pooling | U transform) ------
__global__ void prep_kernel(const float* __restrict__ x, const float* __restrict__ we) {
    const int b = blockIdx.x, tid = threadIdx.x;
    if (b < 1024) {
        __shared__ float sX[64 * 4 * 36];        // [ci][r][cpad]
        const int i = b >> 6, typ = (b >> 2) & 15, ciq = b & 3;
        for (int idx = tid; idx < 64 * 4; idx += 256) {
            sX[idx * 36 + 0] = 0.f;
            sX[idx * 36 + 33] = 0.f;
        }
        for (int idx = tid; idx < 64 * 4 * 32; idx += 256) {
            int px = idx & 31, r = (idx >> 5) & 3, ci = idx >> 7;
            int gy = 2 * typ - 1 + r;
            float v = 0.f;
            if ((unsigned)gy < 32u)
                v = x[((size_t)i * CIN + ciq * 64 + ci) * HW + gy * 32 + px];
            sX[(ci * 4 + r) * 36 + px + 1] = v;
        }
        __syncthreads();
        if (tid < 128) {                          // pooling rows 2ty', 2ty'+1
            int ci = tid & 63, r = 1 + (tid >> 6);
            float s = 0.f;
            #pragma unroll 8
            for (int px = 0; px < 32; px++) s += sX[(ci * 4 + r) * 36 + px + 1];
            atomicAdd(&g_pooled[i * CIN + ciq * 64 + ci], s * (1.0f / HW));
        }
        const int ci2 = tid & 31, txg = tid >> 5;
        #pragma unroll
        for (int tt = 0; tt < 2; tt++) {
            const int tx = txg * 2 + tt;
            float Vv[2][4][4];
            #pragma unroll
            for (int h = 0; h < 2; h++) {
                const int ci = ci2 * 2 + h;
                float d[4][4];
                #pragma unroll
                for (int r = 0; r < 4; r++)
                    #pragma unroll
                    for (int c = 0; c < 4; c++)
                        d[r][c] = sX[(ci * 4 + r) * 36 + 2 * tx + c];
                float f[4][4];
                #pragma unroll
                for (int c = 0; c < 4; c++) {
                    f[0][c] = d[0][c] - d[2][c];
                    f[1][c] = d[1][c] + d[2][c];
                    f[2][c] = d[2][c] - d[1][c];
                    f[3][c] = d[1][c] - d[3][c];
                }
                #pragma unroll
                for (int r = 0; r < 4; r++) {
                    Vv[h][r][0] = f[r][0] - f[r][2];
                    Vv[h][r][1] = f[r][1] + f[r][2];
                    Vv[h][r][2] = f[r][2] - f[r][1];
                    Vv[h][r][3] = f[r][1] - f[r][3];
                }
            }
            const int tile = typ * 16 + tx;
            #pragma unroll
            for (int k = 0; k < 16; k++)
                *(uint32_t*)(g_V + (((size_t)(i * 16 + k) * 256 + tile) * 256
                                    + ciq * 64 + ci2 * 2))
                    = pack2(Vv[0][k >> 2][k & 3], Vv[1][k >> 2][k & 3]);
        }
    } else {
        __shared__ float sW[2304];
        const int row = b - 1024;
        const int e = row >> 8, co = row & 255;
        const float* src = we + (size_t)row * 2304;
        for (int k = tid; k < 2304; k += 256) sW[k] = src[k];
        __syncthreads();
        if (tid < 128) {
            float Uv[2][4][4];
            #pragma unroll
            for (int h = 0; h < 2; h++) {
                const int ci = tid * 2 + h;
                float g[3][3];
                #pragma unroll
                for (int r = 0; r < 3; r++)
                    #pragma unroll
                    for (int c = 0; c < 3; c++) g[r][c] = sW[ci * 9 + r * 3 + c];
                float hh[4][3];
                #pragma unroll
                for (int c = 0; c < 3; c++) {
                    hh[0][c] = g[0][c];
                    hh[1][c] = 0.5f * (g[0][c] + g[1][c] + g[2][c]);
                    hh[2][c] = 0.5f * (g[0][c] - g[1][c] + g[2][c]);
                    hh[3][c] = g[2][c];
                }
                #pragma unroll
                for (int r = 0; r < 4; r++) {
                    Uv[h][r][0] = hh[r][0];
                    Uv[h][r][1] = 0.5f * (hh[r][0] + hh[r][1] + hh[r][2]);
                    Uv[h][r][2] = 0.5f * (hh[r][0] - hh[r][1] + hh[r][2]);
                    Uv[h][r][3] = hh[r][2];
                }
            }
            #pragma unroll
            for (int k = 0; k < 16; k++)
                *(uint32_t*)(g_U + (((size_t)(e * 16 + k) * 256 + co) * 256 + tid * 2))
                    = pack2(Uv[0][k >> 2][k & 3], Uv[1][k >> 2][k & 3]);
        }
    }
}

// ---------------- kernel 2: router finish ----------------
__global__ void router_finish_kernel(const float* __restrict__ wc,
                                     const float* __restrict__ bc) {
    __shared__ float sLog[BATCH][NE];
    const int tid = threadIdx.x;
    const int b = tid >> 3, e = tid & 7;
    const float* p = g_pooled + b * CIN;
    const float* w = wc + e * CIN;
    float sum = 0.f;
    #pragma unroll 8
    for (int k = 0; k < CIN; k++) sum += p[k] * w[k];
    sLog[b][e] = sum + bc[e];
    __syncthreads();
    if (tid < BATCH) {
        float best = sLog[tid][0]; int bi = 0;
        #pragma unroll
        for (int ee = 1; ee < NE; ee++)
            if (sLog[tid][ee] > best) { best = sLog[tid][ee]; bi = ee; }
        g_decisions[tid] = bi;
    }
}

// ---------------- kernel 3: Winograd HMMA GEMM + fused output transform -----
__global__ void __launch_bounds__(256, 1)
gemm_kernel(const float* __restrict__ be, float* __restrict__ out) {
    extern __shared__ __align__(16) char dynraw[];
    char* dyn = (char*)(((uintptr_t)dynraw + 1023) & ~(uintptr_t)1023);
    const uint32_t dynu = smem_u32(dyn);

    __shared__ int sDec[BATCH];
    const int tid = threadIdx.x;
    const int ttile = blockIdx.x, mtile = blockIdx.y, pair = blockIdx.z;
    const int i = pair & 15, e = pair >> 4;

    if (tid < BATCH) sDec[tid] = g_decisions[tid];
    __syncthreads();
    bool need = false;
    #pragma unroll
    for (int j = 0; j < BATCH; j++) need |= (sDec[j] == e);
    if (!need) return;

    const int lane = tid & 31, wid = tid >> 5;
    const int wm = wid & 3, wn = wid >> 2;      // 4x2 warps: 16co x 32tiles

    float Y[4][4][2][2];
    float M[4][4];
    #pragma unroll
    for (int na = 0; na < 4; na++)
        #pragma unroll
        for (int c = 0; c < 4; c++) {
            M[na][c] = 0.f;
            #pragma unroll
            for (int y = 0; y < 2; y++)
                #pragma unroll
                for (int xx = 0; xx < 2; xx++) Y[na][c][y][xx] = 0.f;
        }

    // A rows = co, B rows = tile(n); BOTH non-trans (R10-proven pairing)
    const uint32_t aFragBase = (uint32_t)((wm * 16 + (lane & 15)) * 128 + ((lane >> 4) << 4));
    uint32_t bFragBase[2];
    #pragma unroll
    for (int nb = 0; nb < 2; nb++)
        bFragBase[nb] = (uint32_t)((wn * 32 + nb * 16 + (lane & 7) + ((lane >> 4) << 3)) * 128
                                   + (((lane >> 3) & 1) << 4));

    const int rowL = tid >> 2, colL = (tid & 3) * 2;
    const __half* aRow = g_U + ((size_t)(e * 16) * 256 + mtile * 64 + rowL) * 256;
    const __half* bRow = g_V + ((size_t)(i * 16) * 256 + ttile * 64 + rowL) * 256;

    auto load_stage = [&](int buf, int it) {
        const int k = it >> 1, q = it & 1;
        const uint32_t st = dynu + buf * STAGE;
        const char* aSrc = (const char*)(aRow + (size_t)k * 65536) + q * 256;
        const char* bSrc = (const char*)(bRow + (size_t)k * 65536) + q * 256;
        #pragma unroll
        for (int h = 0; h < 2; h++) {
            #pragma unroll
            for (int cc = 0; cc < 2; cc++) {
                const uint32_t so = SWZ(rowL * 128 + (colL + cc) * 16);
                const int go = h * 128 + (colL + cc) * 16;
                CP_ASYNC16(st + h * 8192 + so, aSrc + go);
                CP_ASYNC16(st + 16384 + h * 8192 + so, bSrc + go);
            }
        }
    };

    load_stage(0, 0); CP_COMMIT();
    load_stage(1, 1); CP_COMMIT();
    load_stage(2, 2); CP_COMMIT();

    #pragma unroll 1
    for (int it = 0; it < NCHUNK; ++it) {
        CP_WAIT2();
        __syncthreads();
        if (it + 3 < NCHUNK) load_stage((it + 3) & 3, it + 3);
        CP_COMMIT();

        const uint32_t bA = dynu + (it & 3) * STAGE;
        #pragma unroll
        for (int s = 0; s < 8; s++) {
            const uint32_t hA = bA + (s >> 2) * 8192;
            const uint32_t hB = bA + 16384 + (s >> 2) * 8192;
            const uint32_t so = (s & 3) * 32;
            uint32_t af[4], bf[2][4];
            LDSM_X4(af, hA + SWZ(aFragBase + so));
            LDSM_X4(bf[0], hB + SWZ(bFragBase[0] + so));
            LDSM_X4(bf[1], hB + SWZ(bFragBase[1] + so));
            MMA16816(M[0], af, bf[0][0], bf[0][1]);
            MMA16816(M[1], af, bf[0][2], bf[0][3]);
            MMA16816(M[2], af, bf[1][0], bf[1][1]);
            MMA16816(M[3], af, bf[1][2], bf[1][3]);
        }
        if (it & 1) {   // fold M_k into Y with A^T (.) A output-transform coeffs
            const int k = it >> 1, ky = k >> 2, kx = k & 3;
            const float cy0 = (ky == 3) ? 0.f : 1.f;
            const float cy1 = (ky == 0) ? 0.f : ((ky == 1) ? 1.f : -1.f);
            const float cx0 = (kx == 3) ? 0.f : 1.f;
            const float cx1 = (kx == 0) ? 0.f : ((kx == 1) ? 1.f : -1.f);
            #pragma unroll
            for (int na = 0; na < 4; na++)
                #pragma unroll
                for (int c = 0; c < 4; c++) {
                    const float m = M[na][c];
                    const float a0 = cx0 * m, a1 = cx1 * m;
                    Y[na][c][0][0] += cy0 * a0;
                    Y[na][c][0][1] += cy0 * a1;
                    Y[na][c][1][0] += cy1 * a0;
                    Y[na][c][1][1] += cy1 * a1;
                    M[na][c] = 0.f;
                }
        }
    }

    const int coR = mtile * 64 + wm * 16 + (lane >> 2);
    const float b0 = be[e * 256 + coR], b1 = be[e * 256 + coR + 8];
    #pragma unroll 1
    for (int j = 0; j < BATCH; j++) {
        if (sDec[j] != e) continue;
        float* ob = out + ((size_t)(j * BATCH + i) << 18);
        #pragma unroll
        for (int na = 0; na < 4; na++) {
            const int tile0 = ttile * 64 + wn * 32 + na * 8 + 2 * (lane & 3);
            #pragma unroll
            for (int c = 0; c < 4; c++) {
                const int co = coR + ((c >> 1) << 3);
                const float bias = (c >> 1) ? b1 : b0;
                const int tile = tile0 + (c & 1);
                const int ty = tile >> 4, tx = tile & 15;
                float* p = ob + (size_t)co * HW + ty * 64 + tx * 2;
                float2 v0, v1;
                v0.x = fmaxf(Y[na][c][0][0] + bias, 0.f);
                v0.y = fmaxf(Y[na][c][0][1] + bias, 0.f);
                v1.x = fmaxf(Y[na][c][1][0] + bias, 0.f);
                v1.y = fmaxf(Y[na][c][1][1] + bias, 0.f);
                *(float2*)p = v0;
                *(float2*)(p + 32) = v1;
            }
        }
    }
}

// ---------------------------------------------------------------------------
extern "C" void kernel_launch(void* const* d_in, const int* in_sizes, int n_in,
                              void* d_out, int out_size) {
    const float* x  = (const float*)d_in[0];
    const float* wc = (const float*)d_in[1];
    const float* bc = (const float*)d_in[2];
    const float* we = (const float*)d_in[3];
    const float* be = (const float*)d_in[4];
    float* out = (float*)d_out;

    static int smemSet = 0;
    if (!smemSet) {
        cudaFuncSetAttribute(gemm_kernel, cudaFuncAttributeMaxDynamicSharedMemorySize,
                             SMEM_TOTAL);
        smemSet = 1;
    }

    void* pooledPtr = nullptr;
    cudaGetSymbolAddress(&pooledPtr, g_pooled);
    cudaMemsetAsync(pooledPtr, 0, BATCH * CIN * sizeof(float));

    prep_kernel<<<1024 + 2048, 256>>>(x, we);
    router_finish_kernel<<<1, 128>>>(wc, bc);
    gemm_kernel<<<dim3(4, 4, BATCH * NE), 256, SMEM_TOTAL>>>(be, out);
}

// round 14
// speedup vs baseline: 1.2549x; 1.1089x over previous
#include <cuda_runtime.h>
#include <cuda_fp16.h>
#include <stdint.h>

#define BATCH 16
#define CIN   256
#define COUT  256
#define HW    1024
#define NE    8
#define NCHUNK 32
#define STAGE  49152          /* A 2x16KB + B 2x8KB */
#define NSTAGE 4
#define SMEM_TOTAL (NSTAGE * STAGE + 1024)

__device__ __forceinline__ uint32_t smem_u32(const void* p) {
    uint32_t a;
    asm("{ .reg .u64 t; cvta.to.shared.u64 t, %1; cvt.u32.u64 %0, t; }" : "=r"(a) : "l"(p));
    return a;
}
#define SWZ(off) ((off) ^ (((off) >> 3) & 0x70))

#define CP_ASYNC16(dst, src) \
    asm volatile("cp.async.cg.shared.global [%0], [%1], 16;" :: "r"(dst), "l"(src) : "memory")
#define CP_COMMIT() asm volatile("cp.async.commit_group;" ::: "memory")
#define CP_WAIT2()  asm volatile("cp.async.wait_group 2;" ::: "memory")

#define LDSM_X4(r, addr) \
    asm volatile("ldmatrix.sync.aligned.m8n8.x4.shared.b16 {%0,%1,%2,%3}, [%4];" \
        : "=r"((r)[0]), "=r"((r)[1]), "=r"((r)[2]), "=r"((r)[3]) : "r"(addr))

#define MMA16816(d, a, b0, b1) \
    asm volatile("mma.sync.aligned.m16n8k16.row.col.f32.f16.f16.f32 " \
        "{%0,%1,%2,%3}, {%4,%5,%6,%7}, {%8,%9}, {%0,%1,%2,%3};" \
        : "+f"((d)[0]), "+f"((d)[1]), "+f"((d)[2]), "+f"((d)[3]) \
        : "r"((a)[0]), "r"((a)[1]), "r"((a)[2]), "r"((a)[3]), "r"(b0), "r"(b1))

__device__ int g_decisions[BATCH];
__device__ float g_pooled[BATCH * CIN];
__device__ __align__(256) __half g_U[(size_t)NE * 16 * COUT * CIN];     // U[e][k][co][ci]
__device__ __align__(256) __half g_V[(size_t)BATCH * 16 * 256 * CIN];   // V[i][k][tile][ci]

__device__ __forceinline__ uint32_t pack2(float v0, float v1) {
    __half h0 = __float2half_rn(v0), h1 = __float2half_rn(v1);
    return ((uint32_t)__half_as_ushort(h1) << 16) | __half_as_ushort(h0);
}

// ---------------- kernel 1: prep (V transform + pooling | U transform) ------
__global__ void prep_kernel(const float* __restrict__ x, const float* __restrict__ we) {
    const int b = blockIdx.x, tid = threadIdx.x;
    if (b < 1024) {
        __shared__ float sX[64 * 4 * 36];
        const int i = b >> 6, typ = (b >> 2) & 15, ciq = b & 3;
        for (int idx = tid; idx < 64 * 4; idx += 256) {
            sX[idx * 36 + 0] = 0.f;
            sX[idx * 36 + 33] = 0.f;
        }
        for (int idx = tid; idx < 64 * 4 * 32; idx += 256) {
            int px = idx & 31, r = (idx >> 5) & 3, ci = idx >> 7;
            int gy = 2 * typ - 1 + r;
            float v = 0.f;
            if ((unsigned)gy < 32u)
                v = x[((size_t)i * CIN + ciq * 64 + ci) * HW + gy * 32 + px];
            sX[(ci * 4 + r) * 36 + px + 1] = v;
        }
        __syncthreads();
        if (tid < 128) {
            int ci = tid & 63, r = 1 + (tid >> 6);
            float s = 0.f;
            #pragma unroll 8
            for (int px = 0; px < 32; px++) s += sX[(ci * 4 + r) * 36 + px + 1];
            atomicAdd(&g_pooled[i * CIN + ciq * 64 + ci], s * (1.0f / HW));
        }
        const int ci2 = tid & 31, txg = tid >> 5;
        #pragma unroll
        for (int tt = 0; tt < 2; tt++) {
            const int tx = txg * 2 + tt;
            float Vv[2][4][4];
            #pragma unroll
            for (int h = 0; h < 2; h++) {
                const int ci = ci2 * 2 + h;
                float d[4][4];
                #pragma unroll
                for (int r = 0; r < 4; r++)
                    #pragma unroll
                    for (int c = 0; c < 4; c++)
                        d[r][c] = sX[(ci * 4 + r) * 36 + 2 * tx + c];
                float f[4][4];
                #pragma unroll
                for (int c = 0; c < 4; c++) {
                    f[0][c] = d[0][c] - d[2][c];
                    f[1][c] = d[1][c] + d[2][c];
                    f[2][c] = d[2][c] - d[1][c];
                    f[3][c] = d[1][c] - d[3][c];
                }
                #pragma unroll
                for (int r = 0; r < 4; r++) {
                    Vv[h][r][0] = f[r][0] - f[r][2];
                    Vv[h][r][1] = f[r][1] + f[r][2];
                    Vv[h][r][2] = f[r][2] - f[r][1];
                    Vv[h][r][3] = f[r][1] - f[r][3];
                }
            }
            const int tile = typ * 16 + tx;
            #pragma unroll
            for (int k = 0; k < 16; k++)
                *(uint32_t*)(g_V + (((size_t)(i * 16 + k) * 256 + tile) * 256
                                    + ciq * 64 + ci2 * 2))
                    = pack2(Vv[0][k >> 2][k & 3], Vv[1][k >> 2][k & 3]);
        }
    } else {
        __shared__ float sW[2304];
        const int row = b - 1024;
        const int e = row >> 8, co = row & 255;
        const float* src = we + (size_t)row * 2304;
        for (int k = tid; k < 2304; k += 256) sW[k] = src[k];
        __syncthreads();
        if (tid < 128) {
            float Uv[2][4][4];
            #pragma unroll
            for (int h = 0; h < 2; h++) {
                const int ci = tid * 2 + h;
                float g[3][3];
                #pragma unroll
                for (int r = 0; r < 3; r++)
                    #pragma unroll
                    for (int c = 0; c < 3; c++) g[r][c] = sW[ci * 9 + r * 3 + c];
                float hh[4][3];
                #pragma unroll
                for (int c = 0; c < 3; c++) {
                    hh[0][c] = g[0][c];
                    hh[1][c] = 0.5f * (g[0][c] + g[1][c] + g[2][c]);
                    hh[2][c] = 0.5f * (g[0][c] - g[1][c] + g[2][c]);
                    hh[3][c] = g[2][c];
                }
                #pragma unroll
                for (int r = 0; r < 4; r++) {
                    Uv[h][r][0] = hh[r][0];
                    Uv[h][r][1] = 0.5f * (hh[r][0] + hh[r][1] + hh[r][2]);
                    Uv[h][r][2] = 0.5f * (hh[r][0] - hh[r][1] + hh[r][2]);
                    Uv[h][r][3] = hh[r][2];
                }
            }
            #pragma unroll
            for (int k = 0; k < 16; k++)
                *(uint32_t*)(g_U + (((size_t)(e * 16 + k) * 256 + co) * 256 + tid * 2))
                    = pack2(Uv[0][k >> 2][k & 3], Uv[1][k >> 2][k & 3]);
        }
    }
}

// ---------------- kernel 2: router finish ----------------
__global__ void router_finish_kernel(const float* __restrict__ wc,
                                     const float* __restrict__ bc) {
    __shared__ float sLog[BATCH][NE];
    const int tid = threadIdx.x;
    const int b = tid >> 3, e = tid & 7;
    const float* p = g_pooled + b * CIN;
    const float* w = wc + e * CIN;
    float sum = 0.f;
    #pragma unroll 8
    for (int k = 0; k < CIN; k++) sum += p[k] * w[k];
    sLog[b][e] = sum + bc[e];
    __syncthreads();
    if (tid < BATCH) {
        float best = sLog[tid][0]; int bi = 0;
        #pragma unroll
        for (int ee = 1; ee < NE; ee++)
            if (sLog[tid][ee] > best) { best = sLog[tid][ee]; bi = ee; }
        g_decisions[tid] = bi;
    }
}

// ---------------- kernel 3: Winograd HMMA GEMM, CTA 128co x 64tiles ---------
// 8 warps (4co x 2tile) of 32co x 32tiles. K-chunk 128, 4 stages.
// grid (4 ttile, 2 mtile, 128 pairs), 256 threads.
__global__ void __launch_bounds__(256, 1)
gemm_kernel(const float* __restrict__ be, float* __restrict__ out) {
    extern __shared__ __align__(16) char dynraw[];
    char* dyn = (char*)(((uintptr_t)dynraw + 1023) & ~(uintptr_t)1023);
    const uint32_t dynu = smem_u32(dyn);

    __shared__ int sDec[BATCH];
    const int tid = threadIdx.x;
    const int ttile = blockIdx.x, mtile = blockIdx.y, pair = blockIdx.z;
    const int i = pair & 15, e = pair >> 4;

    if (tid < BATCH) sDec[tid] = g_decisions[tid];
    __syncthreads();
    bool need = false;
    #pragma unroll
    for (int j = 0; j < BATCH; j++) need |= (sDec[j] == e);
    if (!need) return;

    const int lane = tid & 31, wid = tid >> 5;
    const int wm = wid & 3, wn = wid >> 2;      // 4x2 warps: 32co x 32tiles each

    float Y[2][4][4][2][2];                     // [ma][na][c][y][x] = 128
    float M[2][4][4];                           // 32
    #pragma unroll
    for (int ma = 0; ma < 2; ma++)
        #pragma unroll
        for (int na = 0; na < 4; na++)
            #pragma unroll
            for (int c = 0; c < 4; c++) {
                M[ma][na][c] = 0.f;
                Y[ma][na][c][0][0] = 0.f; Y[ma][na][c][0][1] = 0.f;
                Y[ma][na][c][1][0] = 0.f; Y[ma][na][c][1][1] = 0.f;
            }

    uint32_t aFragBase[2], bFragBase[2];
    #pragma unroll
    for (int ma = 0; ma < 2; ma++)
        aFragBase[ma] = (uint32_t)((wm * 32 + ma * 16 + (lane & 15)) * 128
                                   + ((lane >> 4) << 4));
    #pragma unroll
    for (int nb = 0; nb < 2; nb++)
        bFragBase[nb] = (uint32_t)((wn * 32 + nb * 16 + (lane & 7) + ((lane >> 4) << 3)) * 128
                                   + (((lane >> 3) & 1) << 4));

    // loaders: A 128 rows x 256B (8 x16B/thr), B 64 rows x 256B (4 x16B/thr)
    const int rowA = tid >> 1, chA0 = (tid & 1) * 4;
    const int rowB = tid >> 2, chB0 = (tid & 3) * 2;
    const __half* aRow = g_U + ((size_t)(e * 16) * 256 + mtile * 128 + rowA) * 256;
    const __half* bRow = g_V + ((size_t)(i * 16) * 256 + ttile * 64 + rowB) * 256;

    auto load_stage = [&](int buf, int it) {
        const int k = it >> 1, q = it & 1;
        const uint32_t st = dynu + buf * STAGE;
        const char* aSrc = (const char*)(aRow + (size_t)k * 65536) + q * 256;
        const char* bSrc = (const char*)(bRow + (size_t)k * 65536) + q * 256;
        #pragma unroll
        for (int h = 0; h < 2; h++) {
            #pragma unroll
            for (int cc = 0; cc < 4; cc++)
                CP_ASYNC16(st + h * 16384 + SWZ(rowA * 128 + (chA0 + cc) * 16),
                           aSrc + h * 128 + (chA0 + cc) * 16);
            #pragma unroll
            for (int cc = 0; cc < 2; cc++)
                CP_ASYNC16(st + 32768 + h * 8192 + SWZ(rowB * 128 + (chB0 + cc) * 16),
                           bSrc + h * 128 + (chB0 + cc) * 16);
        }
    };

    load_stage(0, 0); CP_COMMIT();
    load_stage(1, 1); CP_COMMIT();
    load_stage(2, 2); CP_COMMIT();

    #pragma unroll 1
    for (int it = 0; it < NCHUNK; ++it) {
        CP_WAIT2();
        __syncthreads();
        if (it + 3 < NCHUNK) load_stage((it + 3) & 3, it + 3);
        CP_COMMIT();

        const uint32_t bA = dynu + (it & 3) * STAGE;
        #pragma unroll
        for (int s = 0; s < 8; s++) {
            const uint32_t hA = bA + (s >> 2) * 16384;
            const uint32_t hB = bA + 32768 + (s >> 2) * 8192;
            const uint32_t so = (s & 3) * 32;
            uint32_t af[2][4], bf[2][4];
            LDSM_X4(af[0], hA + SWZ(aFragBase[0] + so));
            LDSM_X4(af[1], hA + SWZ(aFragBase[1] + so));
            LDSM_X4(bf[0], hB + SWZ(bFragBase[0] + so));
            LDSM_X4(bf[1], hB + SWZ(bFragBase[1] + so));
            #pragma unroll
            for (int ma = 0; ma < 2; ma++)
                #pragma unroll
                for (int nb = 0; nb < 2; nb++) {
                    MMA16816(M[ma][nb * 2],     af[ma], bf[nb][0], bf[nb][1]);
                    MMA16816(M[ma][nb * 2 + 1], af[ma], bf[nb][2], bf[nb][3]);
                }
        }
        if (it & 1) {   // fold M_k into Y (validated R13 coefficients)
            const int k = it >> 1, ky = k >> 2, kx = k & 3;
            const float cy0 = (ky == 3) ? 0.f : 1.f;
            const float cy1 = (ky == 0) ? 0.f : ((ky == 1) ? 1.f : -1.f);
            const float cx0 = (kx == 3) ? 0.f : 1.f;
            const float cx1 = (kx == 0) ? 0.f : ((kx == 1) ? 1.f : -1.f);
            #pragma unroll
            for (int ma = 0; ma < 2; ma++)
                #pragma unroll
                for (int na = 0; na < 4; na++)
                    #pragma unroll
                    for (int c = 0; c < 4; c++) {
                        const float m = M[ma][na][c];
                        const float a0 = cx0 * m, a1 = cx1 * m;
                        Y[ma][na][c][0][0] += cy0 * a0;
                        Y[ma][na][c][0][1] += cy0 * a1;
                        Y[ma][na][c][1][0] += cy1 * a0;
                        Y[ma][na][c][1][1] += cy1 * a1;
                        M[ma][na][c] = 0.f;
                    }
        }
    }

    // ---------------- epilogue ----------------
    float bias[2][2];
    #pragma unroll
    for (int ma = 0; ma < 2; ma++)
        #pragma unroll
        for (int hb = 0; hb < 2; hb++)
            bias[ma][hb] = be[e * 256 + mtile * 128 + wm * 32 + ma * 16 + (lane >> 2) + hb * 8];
    #pragma unroll 1
    for (int j = 0; j < BATCH; j++) {
        if (sDec[j] != e) continue;
        float* ob = out + ((size_t)(j * BATCH + i) << 18);
        #pragma unroll
        for (int ma = 0; ma < 2; ma++) {
            const int coR = mtile * 128 + wm * 32 + ma * 16 + (lane >> 2);
            #pragma unroll
            for (int na = 0; na < 4; na++) {
                const int tile0 = ttile * 64 + wn * 32 + na * 8 + 2 * (lane & 3);
                #pragma unroll
                for (int c = 0; c < 4; c++) {
                    const int co = coR + ((c >> 1) << 3);
                    const float bi = bias[ma][c >> 1];
                    const int tile = tile0 + (c & 1);
                    const int ty = tile >> 4, tx = tile & 15;
                    float* p = ob + (size_t)co * HW + ty * 64 + tx * 2;
                    float2 v0, v1;
                    v0.x = fmaxf(Y[ma][na][c][0][0] + bi, 0.f);
                    v0.y = fmaxf(Y[ma][na][c][0][1] + bi, 0.f);
                    v1.x = fmaxf(Y[ma][na][c][1][0] + bi, 0.f);
                    v1.y = fmaxf(Y[ma][na][c][1][1] + bi, 0.f);
                    *(float2*)p = v0;
                    *(float2*)(p + 32) = v1;
                }
            }
        }
    }
}

// ---------------------------------------------------------------------------
extern "C" void kernel_launch(void* const* d_in, const int* in_sizes, int n_in,
                              void* d_out, int out_size) {
    const float* x  = (const float*)d_in[0];
    const float* wc = (const float*)d_in[1];
    const float* bc = (const float*)d_in[2];
    const float* we = (const float*)d_in[3];
    const float* be = (const float*)d_in[4];
    float* out = (float*)d_out;

    static int smemSet = 0;
    if (!smemSet) {
        cudaFuncSetAttribute(gemm_kernel, cudaFuncAttributeMaxDynamicSharedMemorySize,
                             SMEM_TOTAL);
        smemSet = 1;
    }

    void* pooledPtr = nullptr;
    cudaGetSymbolAddress(&pooledPtr, g_pooled);
    cudaMemsetAsync(pooledPtr, 0, BATCH * CIN * sizeof(float));

    prep_kernel<<<1024 + 2048, 256>>>(x, we);
    router_finish_kernel<<<1, 128>>>(wc, bc);
    gemm_kernel<<<dim3(4, 2, BATCH * NE), 256, SMEM_TOTAL>>>(be, out);
}